// round 7
// baseline (speedup 1.0000x reference)
#include <cuda_runtime.h>
#include <cuda_bf16.h>
#include <math.h>
#include <stdint.h>

// ---------------------------------------------------------------------------
// SwinBlock. tf32 tensor-core GEMMs: BM=256 tile, warp tile 64x32, scalar
// fragment LDS (R4-proven layout), single-sync 3-stage cp.async mainloop.
// tf32 mma attention (R4). Fused shift/window index maps.
// ---------------------------------------------------------------------------

#define TOK     100352
#define CDIM    192
#define HIDDEN  768
#define QKVDIM  576
#define NWIN    2048
#define NHEAD   6
#define HD      32
#define WN      49

__device__ float g_xn  [ (size_t)TOK * CDIM   ];
__device__ float g_qkv [ (size_t)TOK * HIDDEN ];
__device__ float g_attn[ (size_t)TOK * CDIM   ];
__device__ float g_xa  [ (size_t)TOK * CDIM   ];
// tf32-rounded weights, natural [K][N] layout
__device__ float g_wq [ CDIM * QKVDIM ];
__device__ float g_wp [ CDIM * CDIM   ];
__device__ float g_w1 [ CDIM * HIDDEN ];
__device__ float g_w2 [ HIDDEN * CDIM ];

#define F2TF(u, f) \
    asm volatile("cvt.rna.tf32.f32 %0, %1;" : "=r"(u) : "f"(f))

__device__ __forceinline__ float round_tf32(float f) {
    uint32_t u; F2TF(u, f); return __uint_as_float(u);
}

__device__ __forceinline__ int nat_index(int r) {
    int widx = r / WN, n = r % WN;
    int b  = widx >> 6, wi = widx & 63;
    int hs = (wi >> 3) * 7 + n / 7;
    int ws = (wi & 7)  * 7 + n % 7;
    int h = hs + 3; if (h >= 56) h -= 56;
    int w = ws + 3; if (w >= 56) w -= 56;
    return b * 3136 + h * 56 + w;
}

#define MMA_TF32(c, a, b) \
    asm volatile("mma.sync.aligned.m16n8k8.row.col.f32.tf32.tf32.f32 " \
        "{%0,%1,%2,%3},{%4,%5,%6,%7},{%8,%9},{%0,%1,%2,%3};" \
        : "+f"(c[0]), "+f"(c[1]), "+f"(c[2]), "+f"(c[3]) \
        : "r"(a[0]), "r"(a[1]), "r"(a[2]), "r"(a[3]), "r"(b[0]), "r"(b[1]))

#define CPA16(dst, src) \
    asm volatile("cp.async.cg.shared.global [%0], [%1], 16;" :: "r"(dst), "l"(src))

// ---------------------------------------------------------------------------
// Weight preprocessing: tf32 rounding only (natural layout)
// ---------------------------------------------------------------------------
__global__ void wconv_kernel(const float* __restrict__ a, float* __restrict__ oa, int na,
                             const float* __restrict__ b, float* __restrict__ ob, int nb,
                             const float* __restrict__ c, float* __restrict__ oc, int nc,
                             const float* __restrict__ d, float* __restrict__ od, int nd)
{
    int i = blockIdx.x * blockDim.x + threadIdx.x;
    int stride = gridDim.x * blockDim.x;
    for (int t = i; t < na; t += stride) oa[t] = round_tf32(a[t]);
    for (int t = i; t < nb; t += stride) ob[t] = round_tf32(b[t]);
    for (int t = i; t < nc; t += stride) oc[t] = round_tf32(c[t]);
    for (int t = i; t < nd; t += stride) od[t] = round_tf32(d[t]);
}

// ---------------------------------------------------------------------------
// LayerNorm: one warp per token; output rounded to tf32
// ---------------------------------------------------------------------------
__global__ __launch_bounds__(256) void ln_kernel(
    const float* __restrict__ x, const float* __restrict__ g,
    const float* __restrict__ be, float* __restrict__ out, int gather)
{
    int r = (blockIdx.x * blockDim.x + threadIdx.x) >> 5;
    if (r >= TOK) return;
    int lane = threadIdx.x & 31;
    int src = gather ? nat_index(r) : r;
    const float* p = x + (size_t)src * CDIM;
    float v[6]; float s = 0.f, sq = 0.f;
#pragma unroll
    for (int i = 0; i < 6; i++) {
        v[i] = p[lane + 32 * i];
        s += v[i]; sq += v[i] * v[i];
    }
#pragma unroll
    for (int o = 16; o > 0; o >>= 1) {
        s  += __shfl_xor_sync(0xffffffffu, s,  o);
        sq += __shfl_xor_sync(0xffffffffu, sq, o);
    }
    float mean = s * (1.f / CDIM);
    float var  = sq * (1.f / CDIM) - mean * mean;
    float rstd = rsqrtf(var + 1e-5f);
    float* q = out + (size_t)r * CDIM;
#pragma unroll
    for (int i = 0; i < 6; i++) {
        int c = lane + 32 * i;
        q[c] = round_tf32((v[i] - mean) * rstd * g[c] + be[c]);
    }
}

// ---------------------------------------------------------------------------
// tf32 GEMM:  C[M,N] = A[M,K] @ B[K,N]  (+epilogues)
// Tile 256x64x16, 256 thr, 8 warps (4M x 2N), warp tile 64x32.
// 3-stage cp.async ring, ONE __syncthreads per k-tile (CUTLASS ordering).
// Dynamic smem: 3 * (256*AP + 16*BP) floats = 75264 B.
// ---------------------------------------------------------------------------
#define AP  20     // A smem pitch (floats) -> conflict-free frag LDS
#define BP  72     // B smem pitch (floats) -> conflict-free frag LDS
#define STG 3
#define SSZ (256 * AP + 16 * BP)          // floats per stage (6272)
#define SSZB (SSZ * 4)                    // bytes per stage (25088)
#define GEMM_SMEM (STG * SSZB)            // 75264

enum { EPI_BIAS = 0, EPI_PROJ = 1, EPI_GELU = 2, EPI_RES = 3 };

__device__ __forceinline__ float gelu_exact(float v) {
    return 0.5f * v * (1.0f + erff(v * 0.70710678118654752f));
}

template<int EPI>
__global__ __launch_bounds__(256) void gemm_tc(
    const float* __restrict__ A, const float* __restrict__ B,
    const float* __restrict__ bias, float* __restrict__ C,
    const float* __restrict__ res, int M, int N, int K)
{
    extern __shared__ float smem[];

    const int tid  = threadIdx.x;
    const int lane = tid & 31, warp = tid >> 5;
    const int wm = (warp & 3) * 64;       // warp M offset (4 groups of 64)
    const int wn = (warp >> 2) * 32;      // warp N offset (2 groups of 32)
    const int m0 = blockIdx.y * 256, n0 = blockIdx.x * 64;

    // loader mapping
    const int ar  = tid >> 2;             // A row 0..63 (+64,+128,+192)
    const int ac  = (tid & 3) * 4;        // A k-chunk
    const int brow = tid >> 4;            // B k-row 0..15
    const int bc  = (tid & 15) * 4;       // B n-chunk

    const float* Ag = A + (size_t)(m0 + ar) * K + ac;
    const float* Bg = B + (size_t)brow * N + n0 + bc;

    const uint32_t sa = (uint32_t)__cvta_generic_to_shared(&smem[ar * AP + ac]);
    const uint32_t sb = (uint32_t)__cvta_generic_to_shared(&smem[256 * AP + brow * BP + bc]);
    const uint32_t AROWB = 64 * AP * 4;   // 64 rows of A in bytes

    float acc[4][4][4];
#pragma unroll
    for (int mi = 0; mi < 4; mi++)
#pragma unroll
        for (int ni = 0; ni < 4; ni++)
#pragma unroll
            for (int j = 0; j < 4; j++) acc[mi][ni][j] = 0.f;

    const int KT = K >> 4;

    // prologue: stages 0,1
#pragma unroll
    for (int s = 0; s < STG - 1; s++) {
#pragma unroll
        for (int rr = 0; rr < 4; rr++)
            CPA16(sa + s * SSZB + rr * AROWB, Ag + (size_t)rr * 64 * K + s * 16);
        CPA16(sb + s * SSZB, Bg + (size_t)s * 16 * N);
        asm volatile("cp.async.commit_group;");
    }

    for (int kt = 0; kt < KT; kt++) {
        asm volatile("cp.async.wait_group %0;" :: "n"(STG - 2));
        __syncthreads();

        // issue loads for tile kt+2 AFTER the barrier (its stage is free:
        // it was read in iteration kt-1, whose reads are barrier-ordered)
        if (kt + STG - 1 < KT) {
            const int nb = (kt + STG - 1) % STG;
#pragma unroll
            for (int rr = 0; rr < 4; rr++)
                CPA16(sa + nb * SSZB + rr * AROWB,
                      Ag + (size_t)rr * 64 * K + (kt + STG - 1) * 16);
            CPA16(sb + nb * SSZB, Bg + (size_t)(kt + STG - 1) * 16 * N);
        }
        asm volatile("cp.async.commit_group;");

        const float* as = smem + (kt % STG) * SSZ;
        const float* bs = as + 256 * AP;
#pragma unroll
        for (int ks = 0; ks < 2; ks++) {
            uint32_t af[4][4], bf[4][2];
#pragma unroll
            for (int mi = 0; mi < 4; mi++) {
                const int r = wm + mi * 16 + (lane >> 2);
                const int c = ks * 8 + (lane & 3);
                af[mi][0] = __float_as_uint(as[r * AP + c]);
                af[mi][1] = __float_as_uint(as[(r + 8) * AP + c]);
                af[mi][2] = __float_as_uint(as[r * AP + c + 4]);
                af[mi][3] = __float_as_uint(as[(r + 8) * AP + c + 4]);
            }
#pragma unroll
            for (int ni = 0; ni < 4; ni++) {
                const int cc = wn + ni * 8 + (lane >> 2);
                const int rk = ks * 8 + (lane & 3);
                bf[ni][0] = __float_as_uint(bs[rk * BP + cc]);
                bf[ni][1] = __float_as_uint(bs[(rk + 4) * BP + cc]);
            }
#pragma unroll
            for (int mi = 0; mi < 4; mi++)
#pragma unroll
                for (int ni = 0; ni < 4; ni++)
                    MMA_TF32(acc[mi][ni], af[mi], bf[ni]);
        }
        // no trailing sync: next iteration's barrier protects stage reuse
    }

    // epilogue
    float bv[4][2];
#pragma unroll
    for (int ni = 0; ni < 4; ni++) {
        const int cc = n0 + wn + ni * 8 + (lane & 3) * 2;
        bv[ni][0] = bias[cc]; bv[ni][1] = bias[cc + 1];
    }
#pragma unroll
    for (int mi = 0; mi < 4; mi++) {
#pragma unroll
        for (int h = 0; h < 2; h++) {
            const int row = m0 + wm + mi * 16 + (lane >> 2) + h * 8;
            size_t orow;
            if (EPI == EPI_PROJ) orow = (size_t)nat_index(row) * N;
            else                 orow = (size_t)row * N;
#pragma unroll
            for (int ni = 0; ni < 4; ni++) {
                const int cc = n0 + wn + ni * 8 + (lane & 3) * 2;
                float v0 = acc[mi][ni][2 * h + 0] + bv[ni][0];
                float v1 = acc[mi][ni][2 * h + 1] + bv[ni][1];
                if (EPI == EPI_GELU) {
                    v0 = round_tf32(gelu_exact(v0));
                    v1 = round_tf32(gelu_exact(v1));
                }
                if (EPI == EPI_RES) {
                    v0 += res[(size_t)row * N + cc];
                    v1 += res[(size_t)row * N + cc + 1];
                }
                *(float2*)(C + orow + cc) = make_float2(v0, v1);
            }
        }
    }
}

// ---------------------------------------------------------------------------
// Attention on tensor cores (R4-proven). One block per (window, head).
// ---------------------------------------------------------------------------
#define ATQ 36
#define ATK 72
#define ATS 60
#define ATV 40

__global__ __launch_bounds__(128) void attn_mma_kernel(
    const float* __restrict__ qkv, float* __restrict__ out)
{
    const int widx = blockIdx.x;
    const int head = blockIdx.y;
    __shared__ float Q [64 * ATQ];
    __shared__ float Kt[32 * ATK];
    __shared__ float S [64 * ATS];
    __shared__ float V [56 * ATV];

    const int tid = threadIdx.x;
    const int lane = tid & 31, warp = tid >> 5;
    const int wm = warp * 16;

    for (int t = tid; t < 7 * ATV; t += 128) V[49 * ATV + t] = 0.f;
    for (int t = tid; t < 15 * ATQ; t += 128) Q[49 * ATQ + t] = 0.f;

    for (int t = tid; t < WN * 8; t += 128) {
        int n = t >> 3, d4 = (t & 7) * 4;
        const float* base = qkv + (size_t)(widx * WN + n) * QKVDIM + head * HD + d4;
        float4 q4 = *(const float4*)(base);
        float4 k4 = *(const float4*)(base + CDIM);
        float4 v4 = *(const float4*)(base + 2 * CDIM);
        *(float4*)&Q[n * ATQ + d4] = make_float4(round_tf32(q4.x), round_tf32(q4.y),
                                                 round_tf32(q4.z), round_tf32(q4.w));
        Kt[(d4 + 0) * ATK + n] = round_tf32(k4.x);
        Kt[(d4 + 1) * ATK + n] = round_tf32(k4.y);
        Kt[(d4 + 2) * ATK + n] = round_tf32(k4.z);
        Kt[(d4 + 3) * ATK + n] = round_tf32(k4.w);
        *(float4*)&V[n * ATV + d4] = make_float4(round_tf32(v4.x), round_tf32(v4.y),
                                                 round_tf32(v4.z), round_tf32(v4.w));
    }
    __syncthreads();

    // Phase 1: S = Q @ Kt
    {
        float sacc[7][4];
#pragma unroll
        for (int ni = 0; ni < 7; ni++)
#pragma unroll
            for (int j = 0; j < 4; j++) sacc[ni][j] = 0.f;

#pragma unroll
        for (int ks = 0; ks < 4; ks++) {
            uint32_t a[4];
            const int r = wm + (lane >> 2);
            const int c = ks * 8 + (lane & 3);
            a[0] = __float_as_uint(Q[r * ATQ + c]);
            a[1] = __float_as_uint(Q[(r + 8) * ATQ + c]);
            a[2] = __float_as_uint(Q[r * ATQ + c + 4]);
            a[3] = __float_as_uint(Q[(r + 8) * ATQ + c + 4]);
#pragma unroll
            for (int ni = 0; ni < 7; ni++) {
                uint32_t b[2];
                const int cc = ni * 8 + (lane >> 2);
                const int rk = ks * 8 + (lane & 3);
                b[0] = __float_as_uint(Kt[rk * ATK + cc]);
                b[1] = __float_as_uint(Kt[(rk + 4) * ATK + cc]);
                MMA_TF32(sacc[ni], a, b);
            }
        }
        const float scale = 0.17677669529663687f;
        const int row = wm + (lane >> 2);
#pragma unroll
        for (int ni = 0; ni < 7; ni++) {
            const int col = ni * 8 + (lane & 3) * 2;
            *(float2*)&S[row * ATS + col]       = make_float2(sacc[ni][0] * scale, sacc[ni][1] * scale);
            *(float2*)&S[(row + 8) * ATS + col] = make_float2(sacc[ni][2] * scale, sacc[ni][3] * scale);
        }
    }
    __syncthreads();

    // softmax; store P tf32-rounded; zero pad cols 49..55
    for (int i = warp; i < WN; i += 4) {
        float v0 = S[i * ATS + lane];
        float v1 = (lane < 17) ? S[i * ATS + 32 + lane] : -1e30f;
        float m = fmaxf(v0, v1);
#pragma unroll
        for (int o = 16; o > 0; o >>= 1) m = fmaxf(m, __shfl_xor_sync(0xffffffffu, m, o));
        float e0 = __expf(v0 - m);
        float e1 = (lane < 17) ? __expf(v1 - m) : 0.f;
        float s = e0 + e1;
#pragma unroll
        for (int o = 16; o > 0; o >>= 1) s += __shfl_xor_sync(0xffffffffu, s, o);
        float inv = 1.f / s;
        S[i * ATS + lane] = round_tf32(e0 * inv);
        if (lane < 17)      S[i * ATS + 32 + lane] = round_tf32(e1 * inv);
        else if (lane < 24) S[i * ATS + 32 + lane] = 0.f;
    }
    __syncthreads();

    // Phase 2: O = P @ V
    {
        float oacc[4][4];
#pragma unroll
        for (int ni = 0; ni < 4; ni++)
#pragma unroll
            for (int j = 0; j < 4; j++) oacc[ni][j] = 0.f;

#pragma unroll
        for (int ks = 0; ks < 7; ks++) {
            uint32_t a[4];
            const int r = wm + (lane >> 2);
            const int c = ks * 8 + (lane & 3);
            a[0] = __float_as_uint(S[r * ATS + c]);
            a[1] = __float_as_uint(S[(r + 8) * ATS + c]);
            a[2] = __float_as_uint(S[r * ATS + c + 4]);
            a[3] = __float_as_uint(S[(r + 8) * ATS + c + 4]);
#pragma unroll
            for (int ni = 0; ni < 4; ni++) {
                uint32_t b[2];
                const int cc = ni * 8 + (lane >> 2);
                const int rk = ks * 8 + (lane & 3);
                b[0] = __float_as_uint(V[rk * ATV + cc]);
                b[1] = __float_as_uint(V[(rk + 4) * ATV + cc]);
                MMA_TF32(oacc[ni], a, b);
            }
        }
#pragma unroll
        for (int h = 0; h < 2; h++) {
            const int row = wm + (lane >> 2) + h * 8;
            if (row < WN) {
                float* orow = out + (size_t)(widx * WN + row) * CDIM + head * HD;
#pragma unroll
                for (int ni = 0; ni < 4; ni++) {
                    const int col = ni * 8 + (lane & 3) * 2;
                    *(float2*)(orow + col) = make_float2(round_tf32(oacc[ni][2 * h + 0]),
                                                         round_tf32(oacc[ni][2 * h + 1]));
                }
            }
        }
    }
}

// ---------------------------------------------------------------------------
// Launch
// ---------------------------------------------------------------------------
extern "C" void kernel_launch(void* const* d_in, const int* in_sizes, int n_in,
                              void* d_out, int out_size)
{
    const float* x      = (const float*)d_in[0];
    const float* qkv_w  = (const float*)d_in[1];
    const float* qkv_b  = (const float*)d_in[2];
    const float* proj_w = (const float*)d_in[3];
    const float* proj_b = (const float*)d_in[4];
    const float* g1     = (const float*)d_in[5];
    const float* be1    = (const float*)d_in[6];
    const float* g2     = (const float*)d_in[7];
    const float* be2    = (const float*)d_in[8];
    const float* w1     = (const float*)d_in[9];
    const float* b1     = (const float*)d_in[10];
    const float* w2     = (const float*)d_in[11];
    const float* b2     = (const float*)d_in[12];
    float* out = (float*)d_out;

    float *xn, *qkvbuf, *attnbuf, *xa, *wq, *wp, *wf1, *wf2;
    cudaGetSymbolAddress((void**)&xn,      g_xn);
    cudaGetSymbolAddress((void**)&qkvbuf,  g_qkv);
    cudaGetSymbolAddress((void**)&attnbuf, g_attn);
    cudaGetSymbolAddress((void**)&xa,      g_xa);
    cudaGetSymbolAddress((void**)&wq,      g_wq);
    cudaGetSymbolAddress((void**)&wp,      g_wp);
    cudaGetSymbolAddress((void**)&wf1,     g_w1);
    cudaGetSymbolAddress((void**)&wf2,     g_w2);

    // opt-in dynamic smem (not a stream op; legal under graph capture)
    cudaFuncSetAttribute(gemm_tc<EPI_BIAS>, cudaFuncAttributeMaxDynamicSharedMemorySize, GEMM_SMEM);
    cudaFuncSetAttribute(gemm_tc<EPI_PROJ>, cudaFuncAttributeMaxDynamicSharedMemorySize, GEMM_SMEM);
    cudaFuncSetAttribute(gemm_tc<EPI_GELU>, cudaFuncAttributeMaxDynamicSharedMemorySize, GEMM_SMEM);
    cudaFuncSetAttribute(gemm_tc<EPI_RES>,  cudaFuncAttributeMaxDynamicSharedMemorySize, GEMM_SMEM);

    const int lnBlocks = (TOK * 32) / 256;
    const int MB = TOK / 256;   // 392

    // 0) weights -> tf32 (natural layout)
    wconv_kernel<<<432, 256>>>(qkv_w, wq, CDIM * QKVDIM,
                               proj_w, wp, CDIM * CDIM,
                               w1, wf1, CDIM * HIDDEN,
                               w2, wf2, HIDDEN * CDIM);

    // 1) shift+window gather + LN1 -> xn
    ln_kernel<<<lnBlocks, 256>>>(x, g1, be1, xn, 1);

    // 2) QKV GEMM
    gemm_tc<EPI_BIAS><<<dim3(QKVDIM / 64, MB), 256, GEMM_SMEM>>>(
        xn, wq, qkv_b, qkvbuf, nullptr, TOK, QKVDIM, CDIM);

    // 3) windowed MHA
    attn_mma_kernel<<<dim3(NWIN, NHEAD), 128>>>(qkvbuf, attnbuf);

    // 4) proj GEMM + scatter -> xa
    gemm_tc<EPI_PROJ><<<dim3(CDIM / 64, MB), 256, GEMM_SMEM>>>(
        attnbuf, wp, proj_b, xa, nullptr, TOK, CDIM, CDIM);

    // 5) LN2 -> xn
    ln_kernel<<<lnBlocks, 256>>>(xa, g2, be2, xn, 0);

    // 6) MLP fc1 + GELU -> qkvbuf
    gemm_tc<EPI_GELU><<<dim3(HIDDEN / 64, MB), 256, GEMM_SMEM>>>(
        xn, wf1, b1, qkvbuf, nullptr, TOK, HIDDEN, CDIM);

    // 7) MLP fc2 + residual -> out
    gemm_tc<EPI_RES><<<dim3(CDIM / 64, MB), 256, GEMM_SMEM>>>(
        qkvbuf, wf2, b2, out, xa, TOK, CDIM, HIDDEN);
}

// round 9
// speedup vs baseline: 1.0571x; 1.0571x over previous
#include <cuda_runtime.h>
#include <cuda_bf16.h>
#include <math.h>
#include <stdint.h>

// ---------------------------------------------------------------------------
// SwinBlock. R4 base + (a) ldmatrix A-fragments in GEMM, (b) low-smem
// latency-hiding attention (V aliased into Q buffer, loads before softmax).
// ---------------------------------------------------------------------------

#define TOK     100352
#define CDIM    192
#define HIDDEN  768
#define QKVDIM  576
#define NWIN    2048
#define NHEAD   6
#define HD      32
#define WN      49

__device__ float g_xn  [ (size_t)TOK * CDIM   ];
__device__ float g_qkv [ (size_t)TOK * HIDDEN ];
__device__ float g_attn[ (size_t)TOK * CDIM   ];
__device__ float g_xa  [ (size_t)TOK * CDIM   ];
// tf32-rounded weights, natural [K][N] layout
__device__ float g_wq [ CDIM * QKVDIM ];
__device__ float g_wp [ CDIM * CDIM   ];
__device__ float g_w1 [ CDIM * HIDDEN ];
__device__ float g_w2 [ HIDDEN * CDIM ];

#define F2TF(u, f) \
    asm volatile("cvt.rna.tf32.f32 %0, %1;" : "=r"(u) : "f"(f))

__device__ __forceinline__ float round_tf32(float f) {
    uint32_t u; F2TF(u, f); return __uint_as_float(u);
}

__device__ __forceinline__ int nat_index(int r) {
    int widx = r / WN, n = r % WN;
    int b  = widx >> 6, wi = widx & 63;
    int hs = (wi >> 3) * 7 + n / 7;
    int ws = (wi & 7)  * 7 + n % 7;
    int h = hs + 3; if (h >= 56) h -= 56;
    int w = ws + 3; if (w >= 56) w -= 56;
    return b * 3136 + h * 56 + w;
}

#define MMA_TF32(c, a, b) \
    asm volatile("mma.sync.aligned.m16n8k8.row.col.f32.tf32.tf32.f32 " \
        "{%0,%1,%2,%3},{%4,%5,%6,%7},{%8,%9},{%0,%1,%2,%3};" \
        : "+f"(c[0]), "+f"(c[1]), "+f"(c[2]), "+f"(c[3]) \
        : "r"(a[0]), "r"(a[1]), "r"(a[2]), "r"(a[3]), "r"(b[0]), "r"(b[1]))

#define LDSM4(r0, r1, r2, r3, addr) \
    asm volatile("ldmatrix.sync.aligned.m8n8.x4.shared.b16 {%0,%1,%2,%3}, [%4];" \
        : "=r"(r0), "=r"(r1), "=r"(r2), "=r"(r3) : "r"(addr))

#define CPA16(dst, src) \
    asm volatile("cp.async.cg.shared.global [%0], [%1], 16;" :: "r"(dst), "l"(src))

// ---------------------------------------------------------------------------
// Weight preprocessing: tf32 rounding only (natural layout)
// ---------------------------------------------------------------------------
__global__ void wconv_kernel(const float* __restrict__ a, float* __restrict__ oa, int na,
                             const float* __restrict__ b, float* __restrict__ ob, int nb,
                             const float* __restrict__ c, float* __restrict__ oc, int nc,
                             const float* __restrict__ d, float* __restrict__ od, int nd)
{
    int i = blockIdx.x * blockDim.x + threadIdx.x;
    int stride = gridDim.x * blockDim.x;
    for (int t = i; t < na; t += stride) oa[t] = round_tf32(a[t]);
    for (int t = i; t < nb; t += stride) ob[t] = round_tf32(b[t]);
    for (int t = i; t < nc; t += stride) oc[t] = round_tf32(c[t]);
    for (int t = i; t < nd; t += stride) od[t] = round_tf32(d[t]);
}

// ---------------------------------------------------------------------------
// LayerNorm: one warp per token; output rounded to tf32
// ---------------------------------------------------------------------------
__global__ __launch_bounds__(256) void ln_kernel(
    const float* __restrict__ x, const float* __restrict__ g,
    const float* __restrict__ be, float* __restrict__ out, int gather)
{
    int r = (blockIdx.x * blockDim.x + threadIdx.x) >> 5;
    if (r >= TOK) return;
    int lane = threadIdx.x & 31;
    int src = gather ? nat_index(r) : r;
    const float* p = x + (size_t)src * CDIM;
    float v[6]; float s = 0.f, sq = 0.f;
#pragma unroll
    for (int i = 0; i < 6; i++) {
        v[i] = p[lane + 32 * i];
        s += v[i]; sq += v[i] * v[i];
    }
#pragma unroll
    for (int o = 16; o > 0; o >>= 1) {
        s  += __shfl_xor_sync(0xffffffffu, s,  o);
        sq += __shfl_xor_sync(0xffffffffu, sq, o);
    }
    float mean = s * (1.f / CDIM);
    float var  = sq * (1.f / CDIM) - mean * mean;
    float rstd = rsqrtf(var + 1e-5f);
    float* q = out + (size_t)r * CDIM;
#pragma unroll
    for (int i = 0; i < 6; i++) {
        int c = lane + 32 * i;
        q[c] = round_tf32((v[i] - mean) * rstd * g[c] + be[c]);
    }
}

// ---------------------------------------------------------------------------
// tf32 GEMM (R4 config):  C[M,N] = A[M,K] @ B[K,N]  (+epilogues)
// Tile 128x64x16, 256 thr, 8 warps (4M x 2N), warp tile 32x32, 3-stage ring.
// A fragments via ldmatrix.x4 (R5-verified mapping); B scalar LDS.
// ---------------------------------------------------------------------------
#define AP 20
#define BP 72
#define STG 3

enum { EPI_BIAS = 0, EPI_PROJ = 1, EPI_GELU = 2, EPI_RES = 3 };

__device__ __forceinline__ float gelu_exact(float v) {
    return 0.5f * v * (1.0f + erff(v * 0.70710678118654752f));
}

template<int EPI>
__global__ __launch_bounds__(256) void gemm_tc(
    const float* __restrict__ A, const float* __restrict__ B,
    const float* __restrict__ bias, float* __restrict__ C,
    const float* __restrict__ res, int M, int N, int K)
{
    __shared__ __align__(16) float As[STG][128 * AP];
    __shared__ __align__(16) float Bs[STG][16 * BP];

    const int tid  = threadIdx.x;
    const int lane = tid & 31, warp = tid >> 5;
    const int wm = (warp & 3) * 32;
    const int wn = (warp >> 2) * 32;
    const int m0 = blockIdx.y * 128, n0 = blockIdx.x * 64;

    const int ar  = tid >> 2;
    const int ac  = (tid & 3) * 4;
    const int bkr = tid >> 4;
    const int bc  = (tid & 15) * 4;

    const float* Ag0 = A + (size_t)(m0 + ar) * K + ac;
    const float* Ag1 = Ag0 + (size_t)64 * K;
    const float* Bg  = B + (size_t)bkr * N + n0 + bc;

    const uint32_t sa0 = (uint32_t)__cvta_generic_to_shared(&As[0][ar * AP + ac]);
    const uint32_t sa1 = (uint32_t)__cvta_generic_to_shared(&As[0][(ar + 64) * AP + ac]);
    const uint32_t sb  = (uint32_t)__cvta_generic_to_shared(&Bs[0][bkr * BP + bc]);
    const uint32_t ASTB = sizeof(float) * 128 * AP;
    const uint32_t BSTB = sizeof(float) * 16 * BP;

    // ldmatrix A source address (per-lane; buffer 0, ks=0):
    // matrices: m0=(rows wm..+7, cols 0..3) m1=(+8..15, 0..3) m2=(0..7,4..7) m3=(+8..15,4..7)
    const int a_row = wm + ((lane >> 3) & 1) * 8 + (lane & 7);
    const int a_col = (lane >> 4) * 4;
    const uint32_t aAddr = (uint32_t)__cvta_generic_to_shared(&As[0][a_row * AP + a_col]);

    float acc[2][4][4];
#pragma unroll
    for (int mi = 0; mi < 2; mi++)
#pragma unroll
        for (int ni = 0; ni < 4; ni++)
#pragma unroll
            for (int j = 0; j < 4; j++) acc[mi][ni][j] = 0.f;

    const int KT = K >> 4;

#pragma unroll
    for (int s = 0; s < STG - 1; s++) {
        CPA16(sa0 + s * ASTB, Ag0 + s * 16);
        CPA16(sa1 + s * ASTB, Ag1 + s * 16);
        CPA16(sb  + s * BSTB, Bg + (size_t)s * 16 * N);
        asm volatile("cp.async.commit_group;");
    }

    for (int kt = 0; kt < KT; kt++) {
        if (kt + 2 < KT) {
            const int nb = (kt + 2) % STG;
            CPA16(sa0 + nb * ASTB, Ag0 + (kt + 2) * 16);
            CPA16(sa1 + nb * ASTB, Ag1 + (kt + 2) * 16);
            CPA16(sb  + nb * BSTB, Bg + (size_t)(kt + 2) * 16 * N);
        }
        asm volatile("cp.async.commit_group;");
        asm volatile("cp.async.wait_group 2;");
        __syncthreads();

        const uint32_t aoff = (kt % STG) * ASTB;
        const float* bs = Bs[kt % STG];
#pragma unroll
        for (int ks = 0; ks < 2; ks++) {
            uint32_t af[2][4], bf[4][2];
            LDSM4(af[0][0], af[0][1], af[0][2], af[0][3], aAddr + aoff + ks * 32);
            LDSM4(af[1][0], af[1][1], af[1][2], af[1][3],
                  aAddr + aoff + 16 * AP * 4 + ks * 32);
#pragma unroll
            for (int ni = 0; ni < 4; ni++) {
                const int cc = wn + ni * 8 + (lane >> 2);
                const int rk = ks * 8 + (lane & 3);
                bf[ni][0] = __float_as_uint(bs[rk * BP + cc]);
                bf[ni][1] = __float_as_uint(bs[(rk + 4) * BP + cc]);
            }
#pragma unroll
            for (int mi = 0; mi < 2; mi++)
#pragma unroll
                for (int ni = 0; ni < 4; ni++)
                    MMA_TF32(acc[mi][ni], af[mi], bf[ni]);
        }
        __syncthreads();
    }

    // epilogue
#pragma unroll
    for (int mi = 0; mi < 2; mi++) {
#pragma unroll
        for (int h = 0; h < 2; h++) {
            const int row = m0 + wm + mi * 16 + (lane >> 2) + h * 8;
            size_t orow;
            if (EPI == EPI_PROJ) orow = (size_t)nat_index(row) * N;
            else                 orow = (size_t)row * N;
#pragma unroll
            for (int ni = 0; ni < 4; ni++) {
                const int cc = n0 + wn + ni * 8 + (lane & 3) * 2;
                float v0 = acc[mi][ni][2 * h + 0] + bias[cc];
                float v1 = acc[mi][ni][2 * h + 1] + bias[cc + 1];
                if (EPI == EPI_GELU) {
                    v0 = round_tf32(gelu_exact(v0));
                    v1 = round_tf32(gelu_exact(v1));
                }
                if (EPI == EPI_RES) {
                    v0 += res[(size_t)row * N + cc];
                    v1 += res[(size_t)row * N + cc + 1];
                }
                *(float2*)(C + orow + cc) = make_float2(v0, v1);
            }
        }
    }
}

// ---------------------------------------------------------------------------
// Attention on tensor cores. One block per (window, head), 128 thr.
// Low-smem variant: V aliases Q's buffer (Q dead after phase 1);
// V global loads issued before softmax to hide latency.
// smem = 64*36 + 32*56 + 64*60 floats = 31 KB -> 7 blocks/SM.
// ---------------------------------------------------------------------------
#define ATQ  36   // Q pitch (rows 64)            : (l>>2)*36+(l&3)  distinct mod 32
#define ATVP 40   // V pitch (rows 56, same buf)  : (l&3)*40+(l>>2)  distinct mod 32
#define ATK  56   // Kt pitch (rows 32)           : (l&3)*56+(l>>2)  distinct mod 32
#define ATS  60   // S pitch (rows 64)            : (l>>2)*60+(l&3)  distinct mod 32

__global__ __launch_bounds__(128) void attn_mma_kernel(
    const float* __restrict__ qkv, float* __restrict__ out)
{
    const int widx = blockIdx.x;
    const int head = blockIdx.y;
    __shared__ float QV[64 * ATQ];    // Q (64x32 @36) then V (56x32 @40)
    __shared__ float Kt[32 * ATK];
    __shared__ float S [64 * ATS];

    const int tid = threadIdx.x;
    const int lane = tid & 31, warp = tid >> 5;
    const int wm = warp * 16;
    const float* wbase = qkv + (size_t)(widx * WN) * QKVDIM + head * HD;

    // zero Q pad rows 49..63
    for (int t = tid; t < 15 * ATQ; t += 128) QV[49 * ATQ + t] = 0.f;

    // ---- batched Q,K loads (all LDGs before stores) ----
    float4 qa[4], ka[4]; int ids[4]; int nt = 0;
#pragma unroll 4
    for (int t = tid; t < WN * 8; t += 128) {
        const float* base = wbase + (size_t)(t >> 3) * QKVDIM + (t & 7) * 4;
        qa[nt] = *(const float4*)(base);
        ka[nt] = *(const float4*)(base + CDIM);
        ids[nt] = t; nt++;
    }
#pragma unroll 4
    for (int i = 0; i < nt; i++) {
        int n = ids[i] >> 3, d4 = (ids[i] & 7) * 4;
        *(float4*)&QV[n * ATQ + d4] = make_float4(round_tf32(qa[i].x), round_tf32(qa[i].y),
                                                  round_tf32(qa[i].z), round_tf32(qa[i].w));
        Kt[(d4 + 0) * ATK + n] = round_tf32(ka[i].x);
        Kt[(d4 + 1) * ATK + n] = round_tf32(ka[i].y);
        Kt[(d4 + 2) * ATK + n] = round_tf32(ka[i].z);
        Kt[(d4 + 3) * ATK + n] = round_tf32(ka[i].w);
    }
    __syncthreads();

    // ---- Phase 1: S = Q @ Kt ----
    {
        float sacc[7][4];
#pragma unroll
        for (int ni = 0; ni < 7; ni++)
#pragma unroll
            for (int j = 0; j < 4; j++) sacc[ni][j] = 0.f;

#pragma unroll
        for (int ks = 0; ks < 4; ks++) {
            uint32_t a[4];
            const int r = wm + (lane >> 2);
            const int c = ks * 8 + (lane & 3);
            a[0] = __float_as_uint(QV[r * ATQ + c]);
            a[1] = __float_as_uint(QV[(r + 8) * ATQ + c]);
            a[2] = __float_as_uint(QV[r * ATQ + c + 4]);
            a[3] = __float_as_uint(QV[(r + 8) * ATQ + c + 4]);
#pragma unroll
            for (int ni = 0; ni < 7; ni++) {
                uint32_t b[2];
                const int cc = ni * 8 + (lane >> 2);
                const int rk = ks * 8 + (lane & 3);
                b[0] = __float_as_uint(Kt[rk * ATK + cc]);
                b[1] = __float_as_uint(Kt[(rk + 4) * ATK + cc]);
                MMA_TF32(sacc[ni], a, b);
            }
        }
        const float scale = 0.17677669529663687f;
        const int row = wm + (lane >> 2);
#pragma unroll
        for (int ni = 0; ni < 7; ni++) {
            const int col = ni * 8 + (lane & 3) * 2;
            *(float2*)&S[row * ATS + col]       = make_float2(sacc[ni][0] * scale, sacc[ni][1] * scale);
            *(float2*)&S[(row + 8) * ATS + col] = make_float2(sacc[ni][2] * scale, sacc[ni][3] * scale);
        }
    }
    __syncthreads();   // Q reads done -> QV buffer reusable for V

    // ---- issue V LDGs now; latency hides behind softmax ----
    float4 va[4]; int vn = 0;
#pragma unroll 4
    for (int t = tid; t < WN * 8; t += 128) {
        const float* base = wbase + (size_t)(t >> 3) * QKVDIM + (t & 7) * 4;
        va[vn] = *(const float4*)(base + 2 * CDIM);
        ids[vn] = t; vn++;
    }

    // ---- softmax; store P tf32-rounded; zero pad cols 49..55 ----
    for (int i = warp; i < WN; i += 4) {
        float v0 = S[i * ATS + lane];
        float v1 = (lane < 17) ? S[i * ATS + 32 + lane] : -1e30f;
        float m = fmaxf(v0, v1);
#pragma unroll
        for (int o = 16; o > 0; o >>= 1) m = fmaxf(m, __shfl_xor_sync(0xffffffffu, m, o));
        float e0 = __expf(v0 - m);
        float e1 = (lane < 17) ? __expf(v1 - m) : 0.f;
        float s = e0 + e1;
#pragma unroll
        for (int o = 16; o > 0; o >>= 1) s += __shfl_xor_sync(0xffffffffu, s, o);
        float inv = 1.f / s;
        S[i * ATS + lane] = round_tf32(e0 * inv);
        if (lane < 17)      S[i * ATS + 32 + lane] = round_tf32(e1 * inv);
        else if (lane < 24) S[i * ATS + 32 + lane] = 0.f;
    }

    // ---- store V into QV (pitch 40) + zero its pad rows ----
#pragma unroll 4
    for (int i = 0; i < vn; i++) {
        int n = ids[i] >> 3, d4 = (ids[i] & 7) * 4;
        *(float4*)&QV[n * ATVP + d4] = make_float4(round_tf32(va[i].x), round_tf32(va[i].y),
                                                   round_tf32(va[i].z), round_tf32(va[i].w));
    }
    for (int t = tid; t < 7 * ATVP; t += 128) QV[49 * ATVP + t] = 0.f;
    __syncthreads();

    // ---- Phase 2: O = P @ V ----
    {
        float oacc[4][4];
#pragma unroll
        for (int ni = 0; ni < 4; ni++)
#pragma unroll
            for (int j = 0; j < 4; j++) oacc[ni][j] = 0.f;

#pragma unroll
        for (int ks = 0; ks < 7; ks++) {
            uint32_t a[4];
            const int r = wm + (lane >> 2);
            const int c = ks * 8 + (lane & 3);
            a[0] = __float_as_uint(S[r * ATS + c]);
            a[1] = __float_as_uint(S[(r + 8) * ATS + c]);
            a[2] = __float_as_uint(S[r * ATS + c + 4]);
            a[3] = __float_as_uint(S[(r + 8) * ATS + c + 4]);
#pragma unroll
            for (int ni = 0; ni < 4; ni++) {
                uint32_t b[2];
                const int cc = ni * 8 + (lane >> 2);
                const int rk = ks * 8 + (lane & 3);
                b[0] = __float_as_uint(QV[rk * ATVP + cc]);
                b[1] = __float_as_uint(QV[(rk + 4) * ATVP + cc]);
                MMA_TF32(oacc[ni], a, b);
            }
        }
#pragma unroll
        for (int h = 0; h < 2; h++) {
            const int row = wm + (lane >> 2) + h * 8;
            if (row < WN) {
                float* orow = out + (size_t)(widx * WN + row) * CDIM + head * HD;
#pragma unroll
                for (int ni = 0; ni < 4; ni++) {
                    const int col = ni * 8 + (lane & 3) * 2;
                    *(float2*)(orow + col) = make_float2(round_tf32(oacc[ni][2 * h + 0]),
                                                         round_tf32(oacc[ni][2 * h + 1]));
                }
            }
        }
    }
}

// ---------------------------------------------------------------------------
// Launch
// ---------------------------------------------------------------------------
extern "C" void kernel_launch(void* const* d_in, const int* in_sizes, int n_in,
                              void* d_out, int out_size)
{
    const float* x      = (const float*)d_in[0];
    const float* qkv_w  = (const float*)d_in[1];
    const float* qkv_b  = (const float*)d_in[2];
    const float* proj_w = (const float*)d_in[3];
    const float* proj_b = (const float*)d_in[4];
    const float* g1     = (const float*)d_in[5];
    const float* be1    = (const float*)d_in[6];
    const float* g2     = (const float*)d_in[7];
    const float* be2    = (const float*)d_in[8];
    const float* w1     = (const float*)d_in[9];
    const float* b1     = (const float*)d_in[10];
    const float* w2     = (const float*)d_in[11];
    const float* b2     = (const float*)d_in[12];
    float* out = (float*)d_out;

    float *xn, *qkvbuf, *attnbuf, *xa, *wq, *wp, *wf1, *wf2;
    cudaGetSymbolAddress((void**)&xn,      g_xn);
    cudaGetSymbolAddress((void**)&qkvbuf,  g_qkv);
    cudaGetSymbolAddress((void**)&attnbuf, g_attn);
    cudaGetSymbolAddress((void**)&xa,      g_xa);
    cudaGetSymbolAddress((void**)&wq,      g_wq);
    cudaGetSymbolAddress((void**)&wp,      g_wp);
    cudaGetSymbolAddress((void**)&wf1,     g_w1);
    cudaGetSymbolAddress((void**)&wf2,     g_w2);

    const int lnBlocks = (TOK * 32) / 256;

    // 0) weights -> tf32 (natural layout)
    wconv_kernel<<<432, 256>>>(qkv_w, wq, CDIM * QKVDIM,
                               proj_w, wp, CDIM * CDIM,
                               w1, wf1, CDIM * HIDDEN,
                               w2, wf2, HIDDEN * CDIM);

    // 1) shift+window gather + LN1 -> xn
    ln_kernel<<<lnBlocks, 256>>>(x, g1, be1, xn, 1);

    // 2) QKV GEMM
    gemm_tc<EPI_BIAS><<<dim3(QKVDIM / 64, TOK / 128), 256>>>(
        xn, wq, qkv_b, qkvbuf, nullptr, TOK, QKVDIM, CDIM);

    // 3) windowed MHA
    attn_mma_kernel<<<dim3(NWIN, NHEAD), 128>>>(qkvbuf, attnbuf);

    // 4) proj GEMM + scatter -> xa
    gemm_tc<EPI_PROJ><<<dim3(CDIM / 64, TOK / 128), 256>>>(
        attnbuf, wp, proj_b, xa, nullptr, TOK, CDIM, CDIM);

    // 5) LN2 -> xn
    ln_kernel<<<lnBlocks, 256>>>(xa, g2, be2, xn, 0);

    // 6) MLP fc1 + GELU -> qkvbuf
    gemm_tc<EPI_GELU><<<dim3(HIDDEN / 64, TOK / 128), 256>>>(
        xn, wf1, b1, qkvbuf, nullptr, TOK, HIDDEN, CDIM);

    // 7) MLP fc2 + residual -> out
    gemm_tc<EPI_RES><<<dim3(CDIM / 64, TOK / 128), 256>>>(
        qkvbuf, wf2, b2, out, xa, TOK, CDIM, HIDDEN);
}

// round 10
// speedup vs baseline: 1.1081x; 1.0482x over previous
#include <cuda_runtime.h>
#include <cuda_bf16.h>
#include <math.h>
#include <stdint.h>

// ---------------------------------------------------------------------------
// SwinBlock. R4-proven tf32 mma GEMM + attention. Deltas vs R4:
//  - GEMM mainloop: single __syncthreads per k-tile (loads issued post-barrier)
//  - LayerNorm: float2-vectorized loads/stores
// ---------------------------------------------------------------------------

#define TOK     100352
#define CDIM    192
#define HIDDEN  768
#define QKVDIM  576
#define NWIN    2048
#define NHEAD   6
#define HD      32
#define WN      49

__device__ float g_xn  [ (size_t)TOK * CDIM   ];
__device__ float g_qkv [ (size_t)TOK * HIDDEN ];
__device__ float g_attn[ (size_t)TOK * CDIM   ];
__device__ float g_xa  [ (size_t)TOK * CDIM   ];
// tf32-rounded weights, natural [K][N] layout
__device__ float g_wq [ CDIM * QKVDIM ];
__device__ float g_wp [ CDIM * CDIM   ];
__device__ float g_w1 [ CDIM * HIDDEN ];
__device__ float g_w2 [ HIDDEN * CDIM ];

#define F2TF(u, f) \
    asm volatile("cvt.rna.tf32.f32 %0, %1;" : "=r"(u) : "f"(f))

__device__ __forceinline__ float round_tf32(float f) {
    uint32_t u; F2TF(u, f); return __uint_as_float(u);
}

__device__ __forceinline__ int nat_index(int r) {
    int widx = r / WN, n = r % WN;
    int b  = widx >> 6, wi = widx & 63;
    int hs = (wi >> 3) * 7 + n / 7;
    int ws = (wi & 7)  * 7 + n % 7;
    int h = hs + 3; if (h >= 56) h -= 56;
    int w = ws + 3; if (w >= 56) w -= 56;
    return b * 3136 + h * 56 + w;
}

#define MMA_TF32(c, a, b) \
    asm volatile("mma.sync.aligned.m16n8k8.row.col.f32.tf32.tf32.f32 " \
        "{%0,%1,%2,%3},{%4,%5,%6,%7},{%8,%9},{%0,%1,%2,%3};" \
        : "+f"(c[0]), "+f"(c[1]), "+f"(c[2]), "+f"(c[3]) \
        : "r"(a[0]), "r"(a[1]), "r"(a[2]), "r"(a[3]), "r"(b[0]), "r"(b[1]))

#define CPA16(dst, src) \
    asm volatile("cp.async.cg.shared.global [%0], [%1], 16;" :: "r"(dst), "l"(src))

// ---------------------------------------------------------------------------
// Weight preprocessing: tf32 rounding only (natural layout)
// ---------------------------------------------------------------------------
__global__ void wconv_kernel(const float* __restrict__ a, float* __restrict__ oa, int na,
                             const float* __restrict__ b, float* __restrict__ ob, int nb,
                             const float* __restrict__ c, float* __restrict__ oc, int nc,
                             const float* __restrict__ d, float* __restrict__ od, int nd)
{
    int i = blockIdx.x * blockDim.x + threadIdx.x;
    int stride = gridDim.x * blockDim.x;
    for (int t = i; t < na; t += stride) oa[t] = round_tf32(a[t]);
    for (int t = i; t < nb; t += stride) ob[t] = round_tf32(b[t]);
    for (int t = i; t < nc; t += stride) oc[t] = round_tf32(c[t]);
    for (int t = i; t < nd; t += stride) od[t] = round_tf32(d[t]);
}

// ---------------------------------------------------------------------------
// LayerNorm: one warp per token; float2 vectorized; output rounded to tf32
// ---------------------------------------------------------------------------
__global__ __launch_bounds__(256) void ln_kernel(
    const float* __restrict__ x, const float* __restrict__ g,
    const float* __restrict__ be, float* __restrict__ out, int gather)
{
    int r = (blockIdx.x * blockDim.x + threadIdx.x) >> 5;
    if (r >= TOK) return;
    int lane = threadIdx.x & 31;
    int src = gather ? nat_index(r) : r;
    const float2* p = (const float2*)(x + (size_t)src * CDIM);
    float2 v[3]; float s = 0.f, sq = 0.f;
#pragma unroll
    for (int i = 0; i < 3; i++) {
        v[i] = p[lane + 32 * i];
        s  += v[i].x + v[i].y;
        sq += v[i].x * v[i].x + v[i].y * v[i].y;
    }
#pragma unroll
    for (int o = 16; o > 0; o >>= 1) {
        s  += __shfl_xor_sync(0xffffffffu, s,  o);
        sq += __shfl_xor_sync(0xffffffffu, sq, o);
    }
    float mean = s * (1.f / CDIM);
    float var  = sq * (1.f / CDIM) - mean * mean;
    float rstd = rsqrtf(var + 1e-5f);
    float2* q = (float2*)(out + (size_t)r * CDIM);
#pragma unroll
    for (int i = 0; i < 3; i++) {
        int c2 = lane + 32 * i;
        float2 gg = *(const float2*)(g  + 2 * c2);
        float2 bb = *(const float2*)(be + 2 * c2);
        float2 o2;
        o2.x = round_tf32((v[i].x - mean) * rstd * gg.x + bb.x);
        o2.y = round_tf32((v[i].y - mean) * rstd * gg.y + bb.y);
        q[c2] = o2;
    }
}

// ---------------------------------------------------------------------------
// tf32 GEMM (R4 config):  C[M,N] = A[M,K] @ B[K,N]  (+epilogues)
// Tile 128x64x16, 256 thr, 8 warps (4M x 2N), warp tile 32x32, 3-stage ring.
// SINGLE __syncthreads per k-tile: loads for kt+2 issued after the barrier
// (that stage's reads completed in iteration kt-1, which every warp finished
// before arriving at this barrier). wait_group 1 lands stage kt.
// ---------------------------------------------------------------------------
#define AP 20
#define BP 72
#define STG 3

enum { EPI_BIAS = 0, EPI_PROJ = 1, EPI_GELU = 2, EPI_RES = 3 };

__device__ __forceinline__ float gelu_exact(float v) {
    return 0.5f * v * (1.0f + erff(v * 0.70710678118654752f));
}

template<int EPI>
__global__ __launch_bounds__(256) void gemm_tc(
    const float* __restrict__ A, const float* __restrict__ B,
    const float* __restrict__ bias, float* __restrict__ C,
    const float* __restrict__ res, int M, int N, int K)
{
    __shared__ __align__(16) float As[STG][128 * AP];
    __shared__ __align__(16) float Bs[STG][16 * BP];

    const int tid  = threadIdx.x;
    const int lane = tid & 31, warp = tid >> 5;
    const int wm = (warp & 3) * 32;
    const int wn = (warp >> 2) * 32;
    const int m0 = blockIdx.y * 128, n0 = blockIdx.x * 64;

    const int ar  = tid >> 2;
    const int ac  = (tid & 3) * 4;
    const int bkr = tid >> 4;
    const int bc  = (tid & 15) * 4;

    const float* Ag0 = A + (size_t)(m0 + ar) * K + ac;
    const float* Ag1 = Ag0 + (size_t)64 * K;
    const float* Bg  = B + (size_t)bkr * N + n0 + bc;

    const uint32_t sa0 = (uint32_t)__cvta_generic_to_shared(&As[0][ar * AP + ac]);
    const uint32_t sa1 = (uint32_t)__cvta_generic_to_shared(&As[0][(ar + 64) * AP + ac]);
    const uint32_t sb  = (uint32_t)__cvta_generic_to_shared(&Bs[0][bkr * BP + bc]);
    const uint32_t ASTB = sizeof(float) * 128 * AP;
    const uint32_t BSTB = sizeof(float) * 16 * BP;

    float acc[2][4][4];
#pragma unroll
    for (int mi = 0; mi < 2; mi++)
#pragma unroll
        for (int ni = 0; ni < 4; ni++)
#pragma unroll
            for (int j = 0; j < 4; j++) acc[mi][ni][j] = 0.f;

    const int KT = K >> 4;

    // prologue: tiles 0,1 into stages 0,1
#pragma unroll
    for (int s = 0; s < STG - 1; s++) {
        CPA16(sa0 + s * ASTB, Ag0 + s * 16);
        CPA16(sa1 + s * ASTB, Ag1 + s * 16);
        CPA16(sb  + s * BSTB, Bg + (size_t)s * 16 * N);
        asm volatile("cp.async.commit_group;");
    }

    for (int kt = 0; kt < KT; kt++) {
        asm volatile("cp.async.wait_group 1;");   // stage kt landed
        __syncthreads();                          // all warps done reading stage (kt-1)%3

        if (kt + 2 < KT) {
            const int nb = (kt + 2) % STG;        // == (kt-1)%3, now free
            CPA16(sa0 + nb * ASTB, Ag0 + (kt + 2) * 16);
            CPA16(sa1 + nb * ASTB, Ag1 + (kt + 2) * 16);
            CPA16(sb  + nb * BSTB, Bg + (size_t)(kt + 2) * 16 * N);
        }
        asm volatile("cp.async.commit_group;");   // empty group in tail keeps counts

        const float* as = As[kt % STG];
        const float* bs = Bs[kt % STG];
#pragma unroll
        for (int ks = 0; ks < 2; ks++) {
            uint32_t af[2][4], bf[4][2];
#pragma unroll
            for (int mi = 0; mi < 2; mi++) {
                const int r = wm + mi * 16 + (lane >> 2);
                const int c = ks * 8 + (lane & 3);
                af[mi][0] = __float_as_uint(as[r * AP + c]);
                af[mi][1] = __float_as_uint(as[(r + 8) * AP + c]);
                af[mi][2] = __float_as_uint(as[r * AP + c + 4]);
                af[mi][3] = __float_as_uint(as[(r + 8) * AP + c + 4]);
            }
#pragma unroll
            for (int ni = 0; ni < 4; ni++) {
                const int cc = wn + ni * 8 + (lane >> 2);
                const int rk = ks * 8 + (lane & 3);
                bf[ni][0] = __float_as_uint(bs[rk * BP + cc]);
                bf[ni][1] = __float_as_uint(bs[(rk + 4) * BP + cc]);
            }
#pragma unroll
            for (int mi = 0; mi < 2; mi++)
#pragma unroll
                for (int ni = 0; ni < 4; ni++)
                    MMA_TF32(acc[mi][ni], af[mi], bf[ni]);
        }
        // no trailing sync: next iteration's barrier orders stage reuse
    }

    // epilogue
#pragma unroll
    for (int mi = 0; mi < 2; mi++) {
#pragma unroll
        for (int h = 0; h < 2; h++) {
            const int row = m0 + wm + mi * 16 + (lane >> 2) + h * 8;
            size_t orow;
            if (EPI == EPI_PROJ) orow = (size_t)nat_index(row) * N;
            else                 orow = (size_t)row * N;
#pragma unroll
            for (int ni = 0; ni < 4; ni++) {
                const int cc = n0 + wn + ni * 8 + (lane & 3) * 2;
                float v0 = acc[mi][ni][2 * h + 0] + bias[cc];
                float v1 = acc[mi][ni][2 * h + 1] + bias[cc + 1];
                if (EPI == EPI_GELU) {
                    v0 = round_tf32(gelu_exact(v0));
                    v1 = round_tf32(gelu_exact(v1));
                }
                if (EPI == EPI_RES) {
                    v0 += res[(size_t)row * N + cc];
                    v1 += res[(size_t)row * N + cc + 1];
                }
                *(float2*)(C + orow + cc) = make_float2(v0, v1);
            }
        }
    }
}

// ---------------------------------------------------------------------------
// Attention on tensor cores (R4-proven, byte-for-byte). One block per
// (window, head), 128 thr = 4 warps.
// ---------------------------------------------------------------------------
#define ATQ 36
#define ATK 72
#define ATS 60
#define ATV 40

__global__ __launch_bounds__(128) void attn_mma_kernel(
    const float* __restrict__ qkv, float* __restrict__ out)
{
    const int widx = blockIdx.x;
    const int head = blockIdx.y;
    __shared__ float Q [64 * ATQ];
    __shared__ float Kt[32 * ATK];
    __shared__ float S [64 * ATS];
    __shared__ float V [56 * ATV];

    const int tid = threadIdx.x;
    const int lane = tid & 31, warp = tid >> 5;
    const int wm = warp * 16;

    // zero pads: V rows 49..55, Q rows 49..63
    for (int t = tid; t < 7 * ATV; t += 128) V[49 * ATV + t] = 0.f;
    for (int t = tid; t < 15 * ATQ; t += 128) Q[49 * ATQ + t] = 0.f;

    for (int t = tid; t < WN * 8; t += 128) {
        int n = t >> 3, d4 = (t & 7) * 4;
        const float* base = qkv + (size_t)(widx * WN + n) * QKVDIM + head * HD + d4;
        float4 q4 = *(const float4*)(base);
        float4 k4 = *(const float4*)(base + CDIM);
        float4 v4 = *(const float4*)(base + 2 * CDIM);
        *(float4*)&Q[n * ATQ + d4] = make_float4(round_tf32(q4.x), round_tf32(q4.y),
                                                 round_tf32(q4.z), round_tf32(q4.w));
        Kt[(d4 + 0) * ATK + n] = round_tf32(k4.x);
        Kt[(d4 + 1) * ATK + n] = round_tf32(k4.y);
        Kt[(d4 + 2) * ATK + n] = round_tf32(k4.z);
        Kt[(d4 + 3) * ATK + n] = round_tf32(k4.w);
        *(float4*)&V[n * ATV + d4] = make_float4(round_tf32(v4.x), round_tf32(v4.y),
                                                 round_tf32(v4.z), round_tf32(v4.w));
    }
    __syncthreads();

    // Phase 1: S = Q @ Kt
    {
        float sacc[7][4];
#pragma unroll
        for (int ni = 0; ni < 7; ni++)
#pragma unroll
            for (int j = 0; j < 4; j++) sacc[ni][j] = 0.f;

#pragma unroll
        for (int ks = 0; ks < 4; ks++) {
            uint32_t a[4];
            const int r = wm + (lane >> 2);
            const int c = ks * 8 + (lane & 3);
            a[0] = __float_as_uint(Q[r * ATQ + c]);
            a[1] = __float_as_uint(Q[(r + 8) * ATQ + c]);
            a[2] = __float_as_uint(Q[r * ATQ + c + 4]);
            a[3] = __float_as_uint(Q[(r + 8) * ATQ + c + 4]);
#pragma unroll
            for (int ni = 0; ni < 7; ni++) {
                uint32_t b[2];
                const int cc = ni * 8 + (lane >> 2);
                const int rk = ks * 8 + (lane & 3);
                b[0] = __float_as_uint(Kt[rk * ATK + cc]);
                b[1] = __float_as_uint(Kt[(rk + 4) * ATK + cc]);
                MMA_TF32(sacc[ni], a, b);
            }
        }
        const float scale = 0.17677669529663687f;
        const int row = wm + (lane >> 2);
#pragma unroll
        for (int ni = 0; ni < 7; ni++) {
            const int col = ni * 8 + (lane & 3) * 2;
            *(float2*)&S[row * ATS + col]       = make_float2(sacc[ni][0] * scale, sacc[ni][1] * scale);
            *(float2*)&S[(row + 8) * ATS + col] = make_float2(sacc[ni][2] * scale, sacc[ni][3] * scale);
        }
    }
    __syncthreads();

    // softmax; store P tf32-rounded; zero pad cols 49..55
    for (int i = warp; i < WN; i += 4) {
        float v0 = S[i * ATS + lane];
        float v1 = (lane < 17) ? S[i * ATS + 32 + lane] : -1e30f;
        float m = fmaxf(v0, v1);
#pragma unroll
        for (int o = 16; o > 0; o >>= 1) m = fmaxf(m, __shfl_xor_sync(0xffffffffu, m, o));
        float e0 = __expf(v0 - m);
        float e1 = (lane < 17) ? __expf(v1 - m) : 0.f;
        float s = e0 + e1;
#pragma unroll
        for (int o = 16; o > 0; o >>= 1) s += __shfl_xor_sync(0xffffffffu, s, o);
        float inv = 1.f / s;
        S[i * ATS + lane] = round_tf32(e0 * inv);
        if (lane < 17)      S[i * ATS + 32 + lane] = round_tf32(e1 * inv);
        else if (lane < 24) S[i * ATS + 32 + lane] = 0.f;
    }
    __syncthreads();

    // Phase 2: O = P @ V
    {
        float oacc[4][4];
#pragma unroll
        for (int ni = 0; ni < 4; ni++)
#pragma unroll
            for (int j = 0; j < 4; j++) oacc[ni][j] = 0.f;

#pragma unroll
        for (int ks = 0; ks < 7; ks++) {
            uint32_t a[4];
            const int r = wm + (lane >> 2);
            const int c = ks * 8 + (lane & 3);
            a[0] = __float_as_uint(S[r * ATS + c]);
            a[1] = __float_as_uint(S[(r + 8) * ATS + c]);
            a[2] = __float_as_uint(S[r * ATS + c + 4]);
            a[3] = __float_as_uint(S[(r + 8) * ATS + c + 4]);
#pragma unroll
            for (int ni = 0; ni < 4; ni++) {
                uint32_t b[2];
                const int cc = ni * 8 + (lane >> 2);
                const int rk = ks * 8 + (lane & 3);
                b[0] = __float_as_uint(V[rk * ATV + cc]);
                b[1] = __float_as_uint(V[(rk + 4) * ATV + cc]);
                MMA_TF32(oacc[ni], a, b);
            }
        }
#pragma unroll
        for (int h = 0; h < 2; h++) {
            const int row = wm + (lane >> 2) + h * 8;
            if (row < WN) {
                float* orow = out + (size_t)(widx * WN + row) * CDIM + head * HD;
#pragma unroll
                for (int ni = 0; ni < 4; ni++) {
                    const int col = ni * 8 + (lane & 3) * 2;
                    *(float2*)(orow + col) = make_float2(round_tf32(oacc[ni][2 * h + 0]),
                                                         round_tf32(oacc[ni][2 * h + 1]));
                }
            }
        }
    }
}

// ---------------------------------------------------------------------------
// Launch
// ---------------------------------------------------------------------------
extern "C" void kernel_launch(void* const* d_in, const int* in_sizes, int n_in,
                              void* d_out, int out_size)
{
    const float* x      = (const float*)d_in[0];
    const float* qkv_w  = (const float*)d_in[1];
    const float* qkv_b  = (const float*)d_in[2];
    const float* proj_w = (const float*)d_in[3];
    const float* proj_b = (const float*)d_in[4];
    const float* g1     = (const float*)d_in[5];
    const float* be1    = (const float*)d_in[6];
    const float* g2     = (const float*)d_in[7];
    const float* be2    = (const float*)d_in[8];
    const float* w1     = (const float*)d_in[9];
    const float* b1     = (const float*)d_in[10];
    const float* w2     = (const float*)d_in[11];
    const float* b2     = (const float*)d_in[12];
    float* out = (float*)d_out;

    float *xn, *qkvbuf, *attnbuf, *xa, *wq, *wp, *wf1, *wf2;
    cudaGetSymbolAddress((void**)&xn,      g_xn);
    cudaGetSymbolAddress((void**)&qkvbuf,  g_qkv);
    cudaGetSymbolAddress((void**)&attnbuf, g_attn);
    cudaGetSymbolAddress((void**)&xa,      g_xa);
    cudaGetSymbolAddress((void**)&wq,      g_wq);
    cudaGetSymbolAddress((void**)&wp,      g_wp);
    cudaGetSymbolAddress((void**)&wf1,     g_w1);
    cudaGetSymbolAddress((void**)&wf2,     g_w2);

    const int lnBlocks = (TOK * 32) / 256;

    // 0) weights -> tf32 (natural layout)
    wconv_kernel<<<432, 256>>>(qkv_w, wq, CDIM * QKVDIM,
                               proj_w, wp, CDIM * CDIM,
                               w1, wf1, CDIM * HIDDEN,
                               w2, wf2, HIDDEN * CDIM);

    // 1) shift+window gather + LN1 -> xn
    ln_kernel<<<lnBlocks, 256>>>(x, g1, be1, xn, 1);

    // 2) QKV GEMM
    gemm_tc<EPI_BIAS><<<dim3(QKVDIM / 64, TOK / 128), 256>>>(
        xn, wq, qkv_b, qkvbuf, nullptr, TOK, QKVDIM, CDIM);

    // 3) windowed MHA
    attn_mma_kernel<<<dim3(NWIN, NHEAD), 128>>>(qkvbuf, attnbuf);

    // 4) proj GEMM + scatter -> xa
    gemm_tc<EPI_PROJ><<<dim3(CDIM / 64, TOK / 128), 256>>>(
        attnbuf, wp, proj_b, xa, nullptr, TOK, CDIM, CDIM);

    // 5) LN2 -> xn
    ln_kernel<<<lnBlocks, 256>>>(xa, g2, be2, xn, 0);

    // 6) MLP fc1 + GELU -> qkvbuf
    gemm_tc<EPI_GELU><<<dim3(HIDDEN / 64, TOK / 128), 256>>>(
        xn, wf1, b1, qkvbuf, nullptr, TOK, HIDDEN, CDIM);

    // 7) MLP fc2 + residual -> out
    gemm_tc<EPI_RES><<<dim3(CDIM / 64, TOK / 128), 256>>>(
        qkvbuf, wf2, b2, out, xa, TOK, CDIM, HIDDEN);
}

// round 12
// speedup vs baseline: 1.6064x; 1.4497x over previous
#include <cuda_runtime.h>
#include <cuda_fp16.h>
#include <math.h>
#include <stdint.h>

// ---------------------------------------------------------------------------
// SwinBlock. fp16 m16n8k16 tensor-core GEMMs (11-bit significand = tf32
// precision, 2x rate), fp32 accumulate. Weights pre-transposed to [N][K] half.
// tf32 mma attention (R4-proven) with half output. R10 single-sync mainloop.
// ---------------------------------------------------------------------------

#define TOK     100352
#define CDIM    192
#define HIDDEN  768
#define QKVDIM  576
#define NWIN    2048
#define NHEAD   6
#define HD      32
#define WN      49

__device__ __half g_xn  [ (size_t)TOK * CDIM   ];   // LN out (half)
__device__ float  g_qkv [ (size_t)TOK * QKVDIM ];   // qkv (fp32, attention input)
__device__ __half g_attn[ (size_t)TOK * CDIM   ];   // attention out (half)
__device__ float  g_xa  [ (size_t)TOK * CDIM   ];   // proj out / residual (fp32)
__device__ __half g_hid [ (size_t)TOK * HIDDEN ];   // fc1+gelu out (half)
// fp16 weights, TRANSPOSED to [N][K]
__device__ __half g_wq [ QKVDIM * CDIM ];
__device__ __half g_wp [ CDIM * CDIM   ];
__device__ __half g_w1 [ HIDDEN * CDIM ];
__device__ __half g_w2 [ CDIM * HIDDEN ];

#define F2TF(u, f) \
    asm volatile("cvt.rna.tf32.f32 %0, %1;" : "=r"(u) : "f"(f))

__device__ __forceinline__ float round_tf32(float f) {
    uint32_t u; F2TF(u, f); return __uint_as_float(u);
}

__device__ __forceinline__ int nat_index(int r) {
    int widx = r / WN, n = r % WN;
    int b  = widx >> 6, wi = widx & 63;
    int hs = (wi >> 3) * 7 + n / 7;
    int ws = (wi & 7)  * 7 + n % 7;
    int h = hs + 3; if (h >= 56) h -= 56;
    int w = ws + 3; if (w >= 56) w -= 56;
    return b * 3136 + h * 56 + w;
}

#define MMA_TF32(c, a, b) \
    asm volatile("mma.sync.aligned.m16n8k8.row.col.f32.tf32.tf32.f32 " \
        "{%0,%1,%2,%3},{%4,%5,%6,%7},{%8,%9},{%0,%1,%2,%3};" \
        : "+f"(c[0]), "+f"(c[1]), "+f"(c[2]), "+f"(c[3]) \
        : "r"(a[0]), "r"(a[1]), "r"(a[2]), "r"(a[3]), "r"(b[0]), "r"(b[1]))

#define MMA_F16(c, a, b) \
    asm volatile("mma.sync.aligned.m16n8k16.row.col.f32.f16.f16.f32 " \
        "{%0,%1,%2,%3},{%4,%5,%6,%7},{%8,%9},{%0,%1,%2,%3};" \
        : "+f"(c[0]), "+f"(c[1]), "+f"(c[2]), "+f"(c[3]) \
        : "r"(a[0]), "r"(a[1]), "r"(a[2]), "r"(a[3]), "r"(b[0]), "r"(b[1]))

#define CPA16(dst, src) \
    asm volatile("cp.async.cg.shared.global [%0], [%1], 16;" :: "r"(dst), "l"(src))

// ---------------------------------------------------------------------------
// Weight preprocessing: fp16 convert + transpose [K][N] -> [N][K]
// ---------------------------------------------------------------------------
__global__ void wconv_kernel(const float* __restrict__ a, __half* __restrict__ oa, int ka, int na,
                             const float* __restrict__ b, __half* __restrict__ ob, int kb, int nb,
                             const float* __restrict__ c, __half* __restrict__ oc, int kc, int nc,
                             const float* __restrict__ d, __half* __restrict__ od, int kd, int nd)
{
    int i = blockIdx.x * blockDim.x + threadIdx.x;
    int stride = gridDim.x * blockDim.x;
    for (int t = i; t < ka * na; t += stride) {
        int k = t / na, n = t % na;
        oa[n * ka + k] = __float2half_rn(a[t]);
    }
    for (int t = i; t < kb * nb; t += stride) {
        int k = t / nb, n = t % nb;
        ob[n * kb + k] = __float2half_rn(b[t]);
    }
    for (int t = i; t < kc * nc; t += stride) {
        int k = t / nc, n = t % nc;
        oc[n * kc + k] = __float2half_rn(c[t]);
    }
    for (int t = i; t < kd * nd; t += stride) {
        int k = t / nd, n = t % nd;
        od[n * kd + k] = __float2half_rn(d[t]);
    }
}

// ---------------------------------------------------------------------------
// LayerNorm: one warp per token; float2 loads; half output
// ---------------------------------------------------------------------------
__global__ __launch_bounds__(256) void ln_kernel(
    const float* __restrict__ x, const float* __restrict__ g,
    const float* __restrict__ be, __half* __restrict__ out, int gather)
{
    int r = (blockIdx.x * blockDim.x + threadIdx.x) >> 5;
    if (r >= TOK) return;
    int lane = threadIdx.x & 31;
    int src = gather ? nat_index(r) : r;
    const float2* p = (const float2*)(x + (size_t)src * CDIM);
    float2 v[3]; float s = 0.f, sq = 0.f;
#pragma unroll
    for (int i = 0; i < 3; i++) {
        v[i] = p[lane + 32 * i];
        s  += v[i].x + v[i].y;
        sq += v[i].x * v[i].x + v[i].y * v[i].y;
    }
#pragma unroll
    for (int o = 16; o > 0; o >>= 1) {
        s  += __shfl_xor_sync(0xffffffffu, s,  o);
        sq += __shfl_xor_sync(0xffffffffu, sq, o);
    }
    float mean = s * (1.f / CDIM);
    float var  = sq * (1.f / CDIM) - mean * mean;
    float rstd = rsqrtf(var + 1e-5f);
    __half2* q = (__half2*)(out + (size_t)r * CDIM);
#pragma unroll
    for (int i = 0; i < 3; i++) {
        int c2 = lane + 32 * i;
        float2 gg = *(const float2*)(g  + 2 * c2);
        float2 bb = *(const float2*)(be + 2 * c2);
        q[c2] = __floats2half2_rn((v[i].x - mean) * rstd * gg.x + bb.x,
                                  (v[i].y - mean) * rstd * gg.y + bb.y);
    }
}

// ---------------------------------------------------------------------------
// fp16 GEMM:  C[M,N] = A[M,K] @ Bt[N,K]^T  (+epilogues), fp32 accumulate.
// Tile 128x64x32 (halfs), 256 thr, 8 warps (4M x 2N), warp tile 32x32,
// mma m16n8k16, 3-stage cp.async ring, single __syncthreads per k-tile.
// Pitch 40 halfs: (r*20 + lane&3) mod 32 distinct -> conflict-free frags.
// ---------------------------------------------------------------------------
#define APH 40     // A smem pitch (halfs)
#define BPH 40     // B smem pitch (halfs)
#define BKH 32     // k per tile (halfs)
#define STG 3

enum { EPI_BIAS = 0, EPI_PROJ = 1, EPI_GELU = 2, EPI_RES = 3 };

__device__ __forceinline__ float gelu_exact(float v) {
    return 0.5f * v * (1.0f + erff(v * 0.70710678118654752f));
}

template<int EPI>
__global__ __launch_bounds__(256) void gemm_f16(
    const __half* __restrict__ A, const __half* __restrict__ Bt,
    const float* __restrict__ bias, void* __restrict__ Cv,
    const float* __restrict__ res, int M, int N, int K)
{
    __shared__ __align__(16) __half As[STG][128 * APH];
    __shared__ __align__(16) __half Bs[STG][64 * BPH];

    const int tid  = threadIdx.x;
    const int lane = tid & 31, warp = tid >> 5;
    const int wm = (warp & 3) * 32;
    const int wn = (warp >> 2) * 32;
    const int m0 = blockIdx.y * 128, n0 = blockIdx.x * 64;

    // loaders: A rows 0..63 (+64), 8-half (16B) chunks; B n-rows 0..63
    const int ar = tid >> 2;
    const int ac = (tid & 3) * 8;
    const int bn = tid >> 2;
    const int bk = (tid & 3) * 8;

    const __half* Ag0 = A + (size_t)(m0 + ar) * K + ac;
    const __half* Ag1 = Ag0 + (size_t)64 * K;
    const __half* Bg  = Bt + (size_t)(n0 + bn) * K + bk;

    const uint32_t sa0 = (uint32_t)__cvta_generic_to_shared(&As[0][ar * APH + ac]);
    const uint32_t sa1 = (uint32_t)__cvta_generic_to_shared(&As[0][(ar + 64) * APH + ac]);
    const uint32_t sb  = (uint32_t)__cvta_generic_to_shared(&Bs[0][bn * BPH + bk]);
    const uint32_t ASTB = sizeof(__half) * 128 * APH;
    const uint32_t BSTB = sizeof(__half) * 64 * BPH;

    float acc[2][4][4];
#pragma unroll
    for (int mi = 0; mi < 2; mi++)
#pragma unroll
        for (int ni = 0; ni < 4; ni++)
#pragma unroll
            for (int j = 0; j < 4; j++) acc[mi][ni][j] = 0.f;

    const int KT = K / BKH;

    // prologue: tiles 0,1
#pragma unroll
    for (int s = 0; s < STG - 1; s++) {
        CPA16(sa0 + s * ASTB, Ag0 + s * BKH);
        CPA16(sa1 + s * ASTB, Ag1 + s * BKH);
        CPA16(sb  + s * BSTB, Bg + s * BKH);
        asm volatile("cp.async.commit_group;");
    }

    for (int kt = 0; kt < KT; kt++) {
        asm volatile("cp.async.wait_group 1;");
        __syncthreads();

        if (kt + 2 < KT) {
            const int nb = (kt + 2) % STG;
            CPA16(sa0 + nb * ASTB, Ag0 + (kt + 2) * BKH);
            CPA16(sa1 + nb * ASTB, Ag1 + (kt + 2) * BKH);
            CPA16(sb  + nb * BSTB, Bg + (kt + 2) * BKH);
        }
        asm volatile("cp.async.commit_group;");

        const __half* as = As[kt % STG];
        const __half* bs = Bs[kt % STG];
#pragma unroll
        for (int ks = 0; ks < 2; ks++) {
            uint32_t af[2][4], bf[4][2];
            const int cbase = ks * 16 + 2 * (lane & 3);
#pragma unroll
            for (int mi = 0; mi < 2; mi++) {
                const int r = wm + mi * 16 + (lane >> 2);
                af[mi][0] = *(const uint32_t*)&as[r * APH + cbase];
                af[mi][1] = *(const uint32_t*)&as[(r + 8) * APH + cbase];
                af[mi][2] = *(const uint32_t*)&as[r * APH + cbase + 8];
                af[mi][3] = *(const uint32_t*)&as[(r + 8) * APH + cbase + 8];
            }
#pragma unroll
            for (int ni = 0; ni < 4; ni++) {
                const int nn = wn + ni * 8 + (lane >> 2);
                bf[ni][0] = *(const uint32_t*)&bs[nn * BPH + cbase];
                bf[ni][1] = *(const uint32_t*)&bs[nn * BPH + cbase + 8];
            }
#pragma unroll
            for (int mi = 0; mi < 2; mi++)
#pragma unroll
                for (int ni = 0; ni < 4; ni++)
                    MMA_F16(acc[mi][ni], af[mi], bf[ni]);
        }
        // single sync per tile: next iteration's barrier orders stage reuse
    }

    // epilogue
#pragma unroll
    for (int mi = 0; mi < 2; mi++) {
#pragma unroll
        for (int h = 0; h < 2; h++) {
            const int row = m0 + wm + mi * 16 + (lane >> 2) + h * 8;
            size_t orow;
            if (EPI == EPI_PROJ) orow = (size_t)nat_index(row) * N;
            else                 orow = (size_t)row * N;
#pragma unroll
            for (int ni = 0; ni < 4; ni++) {
                const int cc = n0 + wn + ni * 8 + (lane & 3) * 2;
                float v0 = acc[mi][ni][2 * h + 0] + bias[cc];
                float v1 = acc[mi][ni][2 * h + 1] + bias[cc + 1];
                if (EPI == EPI_GELU) {
                    // half output (feeds fc2 A)
                    __half2* Ch = (__half2*)((__half*)Cv + orow + cc);
                    *Ch = __floats2half2_rn(gelu_exact(v0), gelu_exact(v1));
                } else {
                    float* C = (float*)Cv;
                    if (EPI == EPI_RES) {
                        v0 += res[(size_t)row * N + cc];
                        v1 += res[(size_t)row * N + cc + 1];
                    }
                    *(float2*)(C + orow + cc) = make_float2(v0, v1);
                }
            }
        }
    }
}

// ---------------------------------------------------------------------------
// Attention on tensor cores (R4-proven tf32 path), half output.
// One block per (window, head), 128 thr = 4 warps.
// ---------------------------------------------------------------------------
#define ATQ 36
#define ATK 72
#define ATS 60
#define ATV 40

__global__ __launch_bounds__(128) void attn_mma_kernel(
    const float* __restrict__ qkv, __half* __restrict__ out)
{
    const int widx = blockIdx.x;
    const int head = blockIdx.y;
    __shared__ float Q [64 * ATQ];
    __shared__ float Kt[32 * ATK];
    __shared__ float S [64 * ATS];
    __shared__ float V [56 * ATV];

    const int tid = threadIdx.x;
    const int lane = tid & 31, warp = tid >> 5;
    const int wm = warp * 16;

    for (int t = tid; t < 7 * ATV; t += 128) V[49 * ATV + t] = 0.f;
    for (int t = tid; t < 15 * ATQ; t += 128) Q[49 * ATQ + t] = 0.f;

    for (int t = tid; t < WN * 8; t += 128) {
        int n = t >> 3, d4 = (t & 7) * 4;
        const float* base = qkv + (size_t)(widx * WN + n) * QKVDIM + head * HD + d4;
        float4 q4 = *(const float4*)(base);
        float4 k4 = *(const float4*)(base + CDIM);
        float4 v4 = *(const float4*)(base + 2 * CDIM);
        *(float4*)&Q[n * ATQ + d4] = make_float4(round_tf32(q4.x), round_tf32(q4.y),
                                                 round_tf32(q4.z), round_tf32(q4.w));
        Kt[(d4 + 0) * ATK + n] = round_tf32(k4.x);
        Kt[(d4 + 1) * ATK + n] = round_tf32(k4.y);
        Kt[(d4 + 2) * ATK + n] = round_tf32(k4.z);
        Kt[(d4 + 3) * ATK + n] = round_tf32(k4.w);
        *(float4*)&V[n * ATV + d4] = make_float4(round_tf32(v4.x), round_tf32(v4.y),
                                                 round_tf32(v4.z), round_tf32(v4.w));
    }
    __syncthreads();

    // Phase 1: S = Q @ Kt
    {
        float sacc[7][4];
#pragma unroll
        for (int ni = 0; ni < 7; ni++)
#pragma unroll
            for (int j = 0; j < 4; j++) sacc[ni][j] = 0.f;

#pragma unroll
        for (int ks = 0; ks < 4; ks++) {
            uint32_t a[4];
            const int r = wm + (lane >> 2);
            const int c = ks * 8 + (lane & 3);
            a[0] = __float_as_uint(Q[r * ATQ + c]);
            a[1] = __float_as_uint(Q[(r + 8) * ATQ + c]);
            a[2] = __float_as_uint(Q[r * ATQ + c + 4]);
            a[3] = __float_as_uint(Q[(r + 8) * ATQ + c + 4]);
#pragma unroll
            for (int ni = 0; ni < 7; ni++) {
                uint32_t b[2];
                const int cc = ni * 8 + (lane >> 2);
                const int rk = ks * 8 + (lane & 3);
                b[0] = __float_as_uint(Kt[rk * ATK + cc]);
                b[1] = __float_as_uint(Kt[(rk + 4) * ATK + cc]);
                MMA_TF32(sacc[ni], a, b);
            }
        }
        const float scale = 0.17677669529663687f;
        const int row = wm + (lane >> 2);
#pragma unroll
        for (int ni = 0; ni < 7; ni++) {
            const int col = ni * 8 + (lane & 3) * 2;
            *(float2*)&S[row * ATS + col]       = make_float2(sacc[ni][0] * scale, sacc[ni][1] * scale);
            *(float2*)&S[(row + 8) * ATS + col] = make_float2(sacc[ni][2] * scale, sacc[ni][3] * scale);
        }
    }
    __syncthreads();

    // softmax; store P tf32-rounded; zero pad cols 49..55
    for (int i = warp; i < WN; i += 4) {
        float v0 = S[i * ATS + lane];
        float v1 = (lane < 17) ? S[i * ATS + 32 + lane] : -1e30f;
        float m = fmaxf(v0, v1);
#pragma unroll
        for (int o = 16; o > 0; o >>= 1) m = fmaxf(m, __shfl_xor_sync(0xffffffffu, m, o));
        float e0 = __expf(v0 - m);
        float e1 = (lane < 17) ? __expf(v1 - m) : 0.f;
        float s = e0 + e1;
#pragma unroll
        for (int o = 16; o > 0; o >>= 1) s += __shfl_xor_sync(0xffffffffu, s, o);
        float inv = 1.f / s;
        S[i * ATS + lane] = round_tf32(e0 * inv);
        if (lane < 17)      S[i * ATS + 32 + lane] = round_tf32(e1 * inv);
        else if (lane < 24) S[i * ATS + 32 + lane] = 0.f;
    }
    __syncthreads();

    // Phase 2: O = P @ V -> half output
    {
        float oacc[4][4];
#pragma unroll
        for (int ni = 0; ni < 4; ni++)
#pragma unroll
            for (int j = 0; j < 4; j++) oacc[ni][j] = 0.f;

#pragma unroll
        for (int ks = 0; ks < 7; ks++) {
            uint32_t a[4];
            const int r = wm + (lane >> 2);
            const int c = ks * 8 + (lane & 3);
            a[0] = __float_as_uint(S[r * ATS + c]);
            a[1] = __float_as_uint(S[(r + 8) * ATS + c]);
            a[2] = __float_as_uint(S[r * ATS + c + 4]);
            a[3] = __float_as_uint(S[(r + 8) * ATS + c + 4]);
#pragma unroll
            for (int ni = 0; ni < 4; ni++) {
                uint32_t b[2];
                const int cc = ni * 8 + (lane >> 2);
                const int rk = ks * 8 + (lane & 3);
                b[0] = __float_as_uint(V[rk * ATV + cc]);
                b[1] = __float_as_uint(V[(rk + 4) * ATV + cc]);
                MMA_TF32(oacc[ni], a, b);
            }
        }
#pragma unroll
        for (int h = 0; h < 2; h++) {
            const int row = wm + (lane >> 2) + h * 8;
            if (row < WN) {
                __half* orow = out + (size_t)(widx * WN + row) * CDIM + head * HD;
#pragma unroll
                for (int ni = 0; ni < 4; ni++) {
                    const int col = ni * 8 + (lane & 3) * 2;
                    *(__half2*)(orow + col) = __floats2half2_rn(oacc[ni][2 * h + 0],
                                                                oacc[ni][2 * h + 1]);
                }
            }
        }
    }
}

// ---------------------------------------------------------------------------
// Launch
// ---------------------------------------------------------------------------
extern "C" void kernel_launch(void* const* d_in, const int* in_sizes, int n_in,
                              void* d_out, int out_size)
{
    const float* x      = (const float*)d_in[0];
    const float* qkv_w  = (const float*)d_in[1];
    const float* qkv_b  = (const float*)d_in[2];
    const float* proj_w = (const float*)d_in[3];
    const float* proj_b = (const float*)d_in[4];
    const float* g1     = (const float*)d_in[5];
    const float* be1    = (const float*)d_in[6];
    const float* g2     = (const float*)d_in[7];
    const float* be2    = (const float*)d_in[8];
    const float* w1     = (const float*)d_in[9];
    const float* b1     = (const float*)d_in[10];
    const float* w2     = (const float*)d_in[11];
    const float* b2     = (const float*)d_in[12];
    float* out = (float*)d_out;

    __half *xn, *attnbuf, *hid, *wq, *wp, *wf1, *wf2;
    float *qkvbuf, *xa;
    cudaGetSymbolAddress((void**)&xn,      g_xn);
    cudaGetSymbolAddress((void**)&qkvbuf,  g_qkv);
    cudaGetSymbolAddress((void**)&attnbuf, g_attn);
    cudaGetSymbolAddress((void**)&xa,      g_xa);
    cudaGetSymbolAddress((void**)&hid,     g_hid);
    cudaGetSymbolAddress((void**)&wq,      g_wq);
    cudaGetSymbolAddress((void**)&wp,      g_wp);
    cudaGetSymbolAddress((void**)&wf1,     g_w1);
    cudaGetSymbolAddress((void**)&wf2,     g_w2);

    const int lnBlocks = (TOK * 32) / 256;

    // 0) weights -> fp16, transposed [N][K]
    wconv_kernel<<<432, 256>>>(qkv_w, wq, CDIM, QKVDIM,
                               proj_w, wp, CDIM, CDIM,
                               w1, wf1, CDIM, HIDDEN,
                               w2, wf2, HIDDEN, CDIM);

    // 1) shift+window gather + LN1 -> xn (half)
    ln_kernel<<<lnBlocks, 256>>>(x, g1, be1, xn, 1);

    // 2) QKV GEMM (half x half -> fp32)
    gemm_f16<EPI_BIAS><<<dim3(QKVDIM / 64, TOK / 128), 256>>>(
        xn, wq, qkv_b, qkvbuf, nullptr, TOK, QKVDIM, CDIM);

    // 3) windowed MHA -> attnbuf (half)
    attn_mma_kernel<<<dim3(NWIN, NHEAD), 128>>>(qkvbuf, attnbuf);

    // 4) proj GEMM + scatter -> xa (fp32)
    gemm_f16<EPI_PROJ><<<dim3(CDIM / 64, TOK / 128), 256>>>(
        attnbuf, wp, proj_b, xa, nullptr, TOK, CDIM, CDIM);

    // 5) LN2 -> xn (half)
    ln_kernel<<<lnBlocks, 256>>>(xa, g2, be2, xn, 0);

    // 6) MLP fc1 + GELU -> hid (half)
    gemm_f16<EPI_GELU><<<dim3(HIDDEN / 64, TOK / 128), 256>>>(
        xn, wf1, b1, hid, nullptr, TOK, HIDDEN, CDIM);

    // 7) MLP fc2 + residual -> out (fp32)
    gemm_f16<EPI_RES><<<dim3(CDIM / 64, TOK / 128), 256>>>(
        hid, wf2, b2, out, xa, TOK, CDIM, HIDDEN);
}